// round 1
// baseline (speedup 1.0000x reference)
#include <cuda_runtime.h>
#include <math.h>

// SPD log-map via Chebyshev matrix polynomial.
// X = U diag(s) U^T, eigenvalues in [1, b] (b = Gershgorin bound).
// log(X) = p(X), p = degree-DEG Chebyshev expansion of log on [LO, b]:
//   x = c + d*t, c=(b+LO)/2, d=(b-LO)/2
//   log(c + d t) = log(alpha) + 2 * sum_k (-1)^{k+1} beta^k / k * T_k(t)
//   beta = c/d - sqrt((c/d)^2 - 1), alpha = d/(2 beta)
// Recurrence T_{k+1} = 2 X~ T_k - T_{k-1}; all T_k symmetric -> compute only
// upper-triangular 4x4 tiles (136 of them), mirror-write lower triangle.

#define DEG      26
#define LDM      68      // smem row stride (floats): avoids bank conflicts, keeps float4 alignment
#define NTHREADS 256
#define NTILES   136     // 16*17/2 upper 4x4 tiles of a 64x64 matrix
#define MATN     64
#define MATSZ    (MATN * MATN)
#define OUTSZ    2080    // 64*65/2

__global__ void __launch_bounds__(NTHREADS, 1)
spd_log_cheb_kernel(const float* __restrict__ xg, float* __restrict__ outg)
{
    extern __shared__ float sm[];
    float* Xs = sm;                    // X~ (scaled), 64 x LDM
    float* T0 = sm + 1 * MATN * LDM;   // ping
    float* T1 = sm + 2 * MATN * LDM;   // pong
    float* rs = sm + 3 * MATN * LDM;   // 64 row sums + 1 max

    const int t = threadIdx.x;
    const float* X = xg + (size_t)blockIdx.x * MATSZ;

    // ---- load X into smem (coalesced) ----
    #pragma unroll
    for (int e = t; e < MATSZ; e += NTHREADS) {
        Xs[(e >> 6) * LDM + (e & 63)] = X[e];
    }
    __syncthreads();

    // ---- Gershgorin bound: max row abs-sum ----
    if (t < MATN) {
        float s = 0.f;
        #pragma unroll
        for (int j = 0; j < MATN; j++) s += fabsf(Xs[t * LDM + j]);
        rs[t] = s;
    }
    __syncthreads();
    if (t < 32) {
        float m = fmaxf(rs[t], rs[t + 32]);
        #pragma unroll
        for (int o = 16; o > 0; o >>= 1)
            m = fmaxf(m, __shfl_xor_sync(0xffffffffu, m, o));
        if (t == 0) rs[64] = m;
    }
    __syncthreads();

    const float lo = 0.95f;                 // eigenvalues >= 1 (X = PSD + I); margin for fp32
    float bmax = rs[64] * 1.0005f + 1e-3f;  // safety margin on the upper bound
    bmax = fmaxf(bmax, lo + 0.5f);
    const float cc     = 0.5f * (bmax + lo);
    const float dd     = 0.5f * (bmax - lo);
    const float inv_dd = 1.0f / dd;
    const float ratio  = cc * inv_dd;
    const float beta   = ratio - sqrtf(ratio * ratio - 1.0f);
    const float alpha  = dd / (2.0f * beta);
    const float a0     = logf(alpha);

    // ---- scale X~ = (X - c I)/d ; T0 = I ; T1 = X~ ----
    #pragma unroll
    for (int e = t; e < MATSZ; e += NTHREADS) {
        int r = e >> 6, j = e & 63;
        float v = Xs[r * LDM + j];
        v = (v - ((r == j) ? cc : 0.f)) * inv_dd;
        Xs[r * LDM + j] = v;
        T1[r * LDM + j] = v;
        T0[r * LDM + j] = (r == j) ? 1.f : 0.f;
    }
    __syncthreads();

    // ---- tile assignment: thread t < 136 owns upper 4x4 tile (bi, bj), bi<=bj ----
    const bool active = (t < NTILES);
    int bi = 0, bj = 0;
    {
        int tt = active ? t : 0;
        while (tt >= 16 - bi) { tt -= 16 - bi; bi++; }
        bj = bi + tt;
    }
    const int i0 = bi * 4, j0 = bj * 4;

    // ---- accumulator init: a0*I + a1*T1,  a_k = 2*(-1)^{k+1} beta^k / k ----
    float acc[4][4];
    float sgnpow = beta;  // (-1)^{k+1} beta^k at k=1
    if (active) {
        const float a1 = 2.f * sgnpow;
        #pragma unroll
        for (int r = 0; r < 4; r++)
            #pragma unroll
            for (int c = 0; c < 4; c++)
                acc[r][c] = a1 * Xs[(i0 + r) * LDM + j0 + c]
                          + (((i0 + r) == (j0 + c)) ? a0 : 0.f);
    }

    // ---- Chebyshev recurrence with in-place ping-pong ----
    float* Tc = T1;  // T_{k-1} at loop entry of step k
    float* Tp = T0;  // T_{k-2}, overwritten with T_k
    for (int k = 2; k <= DEG; k++) {
        sgnpow = -sgnpow * beta;
        const float ak = 2.f * sgnpow / (float)k;
        if (active) {
            float sum[4][4] = {};
            const float* xr0 = Xs + (i0 + 0) * LDM;
            const float* xr1 = Xs + (i0 + 1) * LDM;
            const float* xr2 = Xs + (i0 + 2) * LDM;
            const float* xr3 = Xs + (i0 + 3) * LDM;
            #pragma unroll 4
            for (int kk = 0; kk < MATN; kk++) {
                const float4 bv = *(const float4*)(Tc + kk * LDM + j0);
                const float v0 = xr0[kk], v1 = xr1[kk], v2 = xr2[kk], v3 = xr3[kk];
                sum[0][0] += v0 * bv.x; sum[0][1] += v0 * bv.y;
                sum[0][2] += v0 * bv.z; sum[0][3] += v0 * bv.w;
                sum[1][0] += v1 * bv.x; sum[1][1] += v1 * bv.y;
                sum[1][2] += v1 * bv.z; sum[1][3] += v1 * bv.w;
                sum[2][0] += v2 * bv.x; sum[2][1] += v2 * bv.y;
                sum[2][2] += v2 * bv.z; sum[2][3] += v2 * bv.w;
                sum[3][0] += v3 * bv.x; sum[3][1] += v3 * bv.y;
                sum[3][2] += v3 * bv.z; sum[3][3] += v3 * bv.w;
            }
            #pragma unroll
            for (int r = 0; r < 4; r++)
                #pragma unroll
                for (int c = 0; c < 4; c++) {
                    // T_k = 2 X~ T_{k-1} - T_{k-2}; each (i,j)/(j,i) pair owned by one thread
                    float v = 2.f * sum[r][c] - Tp[(i0 + r) * LDM + j0 + c];
                    Tp[(i0 + r) * LDM + j0 + c] = v;
                    if (bi != bj) Tp[(j0 + c) * LDM + i0 + r] = v;  // symmetry mirror
                    acc[r][c] += ak * v;
                }
        }
        float* tmp = Tc; Tc = Tp; Tp = tmp;
        __syncthreads();
    }

    // ---- emit upper-triangular flatten (row-major triu order) ----
    if (active) {
        float* o = outg + (size_t)blockIdx.x * OUTSZ;
        #pragma unroll
        for (int r = 0; r < 4; r++)
            #pragma unroll
            for (int c = 0; c < 4; c++) {
                int i = i0 + r, j = j0 + c;
                if (i <= j)
                    o[i * MATN - (i * (i - 1)) / 2 + (j - i)] = acc[r][c];
            }
    }
}

extern "C" void kernel_launch(void* const* d_in, const int* in_sizes, int n_in,
                              void* d_out, int out_size)
{
    const float* x = (const float*)d_in[0];
    float* out = (float*)d_out;
    const int B = in_sizes[0] / MATSZ;

    const int smem_bytes = (3 * MATN * LDM + 65) * (int)sizeof(float);
    cudaFuncSetAttribute(spd_log_cheb_kernel,
                         cudaFuncAttributeMaxDynamicSharedMemorySize, smem_bytes);

    spd_log_cheb_kernel<<<B, NTHREADS, smem_bytes>>>(x, out);
}

// round 2
// speedup vs baseline: 2.1099x; 2.1099x over previous
#include <cuda_runtime.h>
#include <math.h>

// SPD log-map via Chebyshev matrix polynomial.
// X = U diag(s) U^T, eigenvalues in [lo, b] (b = Gershgorin bound).
// log(X) = p(X), degree-DEG Chebyshev expansion of log on [lo, b]:
//   x = c + d*t, c=(b+lo)/2, d=(b-lo)/2
//   log(c + d t) = log(alpha) + 2 * sum_k (-1)^{k+1} beta^k / k * T_k(t)
//   beta = c/d - sqrt((c/d)^2 - 1), alpha = d/(2 beta)
// T_{k+1} = 2 X~ T_k - T_{k-1}; all T_k symmetric -> compute only the 136
// upper 4x4 tiles, mirror-write the lower triangle.
// Key trick: X~ is symmetric, so the A-operand rows are read as contiguous
// float4 from row kk (A[i][kk] == A[kk][i]) -> 2 LDS.128 per 16 FMA.

#define DEG      16
#define LDM      68      // smem row stride (floats): float4-aligned, conflict-friendly
#define NTHREADS 160     // 5 warps; 136 active in main loop (85%)
#define NTILES   136     // 16*17/2 upper 4x4 tiles
#define MATN     64
#define MATSZ    (MATN * MATN)
#define OUTSZ    2080    // 64*65/2

__global__ void __launch_bounds__(NTHREADS)
spd_log_cheb_kernel(const float* __restrict__ xg, float* __restrict__ outg)
{
    extern __shared__ float sm[];
    float* Xs = sm;                    // X~ (scaled), 64 x LDM
    float* T0 = sm + 1 * MATN * LDM;   // ping
    float* T1 = sm + 2 * MATN * LDM;   // pong
    float* rs = sm + 3 * MATN * LDM;   // 64 row sums + 1 max

    const int t = threadIdx.x;
    const float* X = xg + (size_t)blockIdx.x * MATSZ;

    // ---- load X into smem (coalesced) ----
    for (int e = t; e < MATSZ; e += NTHREADS) {
        Xs[(e >> 6) * LDM + (e & 63)] = X[e];
    }
    __syncthreads();

    // ---- Gershgorin bound: max row abs-sum ----
    if (t < MATN) {
        float s = 0.f;
        #pragma unroll
        for (int j = 0; j < MATN; j++) s += fabsf(Xs[t * LDM + j]);
        rs[t] = s;
    }
    __syncthreads();
    if (t < 32) {
        float m = fmaxf(rs[t], rs[t + 32]);
        #pragma unroll
        for (int o = 16; o > 0; o >>= 1)
            m = fmaxf(m, __shfl_xor_sync(0xffffffffu, m, o));
        if (t == 0) rs[64] = m;
    }
    __syncthreads();

    const float lo = 0.95f;                 // eigenvalues >= 1 (X = PSD + I)
    float bmax = rs[64] * 1.0002f + 1e-3f;  // small safety margin
    bmax = fmaxf(bmax, lo + 0.5f);
    const float cc     = 0.5f * (bmax + lo);
    const float dd     = 0.5f * (bmax - lo);
    const float inv_dd = 1.0f / dd;
    const float ratio  = cc * inv_dd;
    const float beta   = ratio - sqrtf(ratio * ratio - 1.0f);
    const float alpha  = dd / (2.0f * beta);
    const float a0     = logf(alpha);

    // ---- scale X~ = (X - c I)/d ; T0 = I ; T1 = X~ ----
    for (int e = t; e < MATSZ; e += NTHREADS) {
        int r = e >> 6, j = e & 63;
        float v = Xs[r * LDM + j];
        v = (v - ((r == j) ? cc : 0.f)) * inv_dd;
        Xs[r * LDM + j] = v;
        T1[r * LDM + j] = v;
        T0[r * LDM + j] = (r == j) ? 1.f : 0.f;
    }
    __syncthreads();

    // ---- tile assignment: thread t < 136 owns upper 4x4 tile (bi, bj), bi<=bj ----
    const bool active = (t < NTILES);
    int bi = 0, bj = 0;
    {
        int tt = active ? t : 0;
        while (tt >= 16 - bi) { tt -= 16 - bi; bi++; }
        bj = bi + tt;
    }
    const int i0 = bi * 4, j0 = bj * 4;

    // ---- accumulator init: a0*I + a1*T1,  a_k = 2*(-1)^{k+1} beta^k / k ----
    float acc[4][4];
    float sgnpow = beta;  // (-1)^{k+1} beta^k at k=1
    if (active) {
        const float a1 = 2.f * sgnpow;
        #pragma unroll
        for (int r = 0; r < 4; r++) {
            const float4 xv = *(const float4*)(Xs + (i0 + r) * LDM + j0);
            acc[r][0] = a1 * xv.x; acc[r][1] = a1 * xv.y;
            acc[r][2] = a1 * xv.z; acc[r][3] = a1 * xv.w;
            int dc = (j0 <= i0 + r) && (i0 + r < j0 + 4) ? (i0 + r - j0) : -1;
            if (dc >= 0) acc[r][dc] += a0;
        }
    }

    // ---- Chebyshev recurrence with in-place ping-pong ----
    float* Tc = T1;  // T_{k-1}
    float* Tp = T0;  // T_{k-2}, overwritten with T_k
    for (int k = 2; k <= DEG; k++) {
        sgnpow = -sgnpow * beta;
        const float ak = 2.f * sgnpow / (float)k;
        if (active) {
            float s00=0.f,s01=0.f,s02=0.f,s03=0.f;
            float s10=0.f,s11=0.f,s12=0.f,s13=0.f;
            float s20=0.f,s21=0.f,s22=0.f,s23=0.f;
            float s30=0.f,s31=0.f,s32=0.f,s33=0.f;
            const float* Xp = Xs + i0;
            const float* Bp = Tc + j0;
            #pragma unroll 8
            for (int kk = 0; kk < MATN; kk++) {
                // A[i0..i0+3][kk] == X~[kk][i0..i0+3] (symmetry) -> contiguous float4
                const float4 av = *(const float4*)(Xp + kk * LDM);
                const float4 bv = *(const float4*)(Bp + kk * LDM);
                s00 += av.x * bv.x; s01 += av.x * bv.y; s02 += av.x * bv.z; s03 += av.x * bv.w;
                s10 += av.y * bv.x; s11 += av.y * bv.y; s12 += av.y * bv.z; s13 += av.y * bv.w;
                s20 += av.z * bv.x; s21 += av.z * bv.y; s22 += av.z * bv.z; s23 += av.z * bv.w;
                s30 += av.w * bv.x; s31 += av.w * bv.y; s32 += av.w * bv.z; s33 += av.w * bv.w;
            }
            // T_k = 2 X~ T_{k-1} - T_{k-2}
            float v[4][4];
            #pragma unroll
            for (int r = 0; r < 4; r++) {
                const float4 pv = *(const float4*)(Tp + (i0 + r) * LDM + j0);
                v[r][0] = 0.f; // placate compiler; overwritten below
                float* vr = v[r];
                float sr0 = (r==0? s00 : r==1? s10 : r==2? s20 : s30);
                float sr1 = (r==0? s01 : r==1? s11 : r==2? s21 : s31);
                float sr2 = (r==0? s02 : r==1? s12 : r==2? s22 : s32);
                float sr3 = (r==0? s03 : r==1? s13 : r==2? s23 : s33);
                vr[0] = 2.f * sr0 - pv.x;
                vr[1] = 2.f * sr1 - pv.y;
                vr[2] = 2.f * sr2 - pv.z;
                vr[3] = 2.f * sr3 - pv.w;
                *(float4*)(Tp + (i0 + r) * LDM + j0) = make_float4(vr[0], vr[1], vr[2], vr[3]);
                acc[r][0] += ak * vr[0]; acc[r][1] += ak * vr[1];
                acc[r][2] += ak * vr[2]; acc[r][3] += ak * vr[3];
            }
            if (bi != bj) {
                #pragma unroll
                for (int c = 0; c < 4; c++) {
                    *(float4*)(Tp + (j0 + c) * LDM + i0) =
                        make_float4(v[0][c], v[1][c], v[2][c], v[3][c]);
                }
            }
        }
        float* tmp = Tc; Tc = Tp; Tp = tmp;
        __syncthreads();
    }

    // ---- emit upper-triangular flatten (row-major triu order) ----
    if (active) {
        float* o = outg + (size_t)blockIdx.x * OUTSZ;
        #pragma unroll
        for (int r = 0; r < 4; r++)
            #pragma unroll
            for (int c = 0; c < 4; c++) {
                int i = i0 + r, j = j0 + c;
                if (i <= j)
                    o[i * MATN - (i * (i - 1)) / 2 + (j - i)] = acc[r][c];
            }
    }
}

extern "C" void kernel_launch(void* const* d_in, const int* in_sizes, int n_in,
                              void* d_out, int out_size)
{
    const float* x = (const float*)d_in[0];
    float* out = (float*)d_out;
    const int B = in_sizes[0] / MATSZ;

    const int smem_bytes = (3 * MATN * LDM + 65) * (int)sizeof(float);
    cudaFuncSetAttribute(spd_log_cheb_kernel,
                         cudaFuncAttributeMaxDynamicSharedMemorySize, smem_bytes);

    spd_log_cheb_kernel<<<B, NTHREADS, smem_bytes>>>(x, out);
}

// round 3
// speedup vs baseline: 4.2126x; 1.9966x over previous
#include <cuda_runtime.h>
#include <math.h>

// SPD log-map via Chebyshev + Paterson-Stockmeyer (Clenshaw in W = T_4).
//
// X SPD, eigen in [lo, b]. X~ = (X - c)/d maps spectrum to [-1,1].
// log(x) = a0 + sum_{k=1}^{13} a_k T_k(t),  a_k = 2(-1)^{k+1} beta^k / k,
//   beta = c/d - sqrt((c/d)^2-1), a0 = log(d/(2 beta)).
// Fold with the exact identity T_q(W) T_r = (T_{4q+r} + T_{4q-r})/2, W = T_4:
//   log(X~...) = sum_{q=0}^{3} T_q(W) P_q,  P_q = combos of {I, T1, T2, T3}.
// Clenshaw in W: b3 = P3; b2 = 2W b3 + P2; b1 = 2W b2 - b3 + P1;
//   S = P0 - b2 + W b1.
// Total 6 matmuls: X*X (also gives bound lammax <= sqrt(gersh(X^2)) and T2
// elementwise), T3, T4=W, and 3 Clenshaw products.
// All operands symmetric -> A rows read as contiguous float4 (A[i][k]=A[k][i]);
// only 136 upper 4x4 tiles computed, mirrored.

#define LDM      68
#define NTHREADS 160
#define NTILES   136
#define MATN     64
#define MATSZ    (MATN * MATN)
#define OUTSZ    2080

__device__ __forceinline__ void mm_tile(const float* __restrict__ A,
                                        const float* __restrict__ B,
                                        int i0, int j0, float s[4][4])
{
    #pragma unroll
    for (int r = 0; r < 4; r++)
        #pragma unroll
        for (int c = 0; c < 4; c++) s[r][c] = 0.f;
    const float* Ap = A + i0;
    const float* Bp = B + j0;
    #pragma unroll 8
    for (int kk = 0; kk < MATN; kk++) {
        const float4 av = *(const float4*)(Ap + kk * LDM);  // A[i0..i0+3][kk] via symmetry
        const float4 bv = *(const float4*)(Bp + kk * LDM);
        s[0][0] += av.x*bv.x; s[0][1] += av.x*bv.y; s[0][2] += av.x*bv.z; s[0][3] += av.x*bv.w;
        s[1][0] += av.y*bv.x; s[1][1] += av.y*bv.y; s[1][2] += av.y*bv.z; s[1][3] += av.y*bv.w;
        s[2][0] += av.z*bv.x; s[2][1] += av.z*bv.y; s[2][2] += av.z*bv.z; s[2][3] += av.z*bv.w;
        s[3][0] += av.w*bv.x; s[3][1] += av.w*bv.y; s[3][2] += av.w*bv.z; s[3][3] += av.w*bv.w;
    }
}

__device__ __forceinline__ void load_tile(const float* __restrict__ M,
                                          int i0, int j0, float v[4][4])
{
    #pragma unroll
    for (int r = 0; r < 4; r++) {
        const float4 t = *(const float4*)(M + (i0 + r) * LDM + j0);
        v[r][0] = t.x; v[r][1] = t.y; v[r][2] = t.z; v[r][3] = t.w;
    }
}

__device__ __forceinline__ void store_tile_sym(float* __restrict__ M,
                                               int i0, int j0, bool offdiag,
                                               const float v[4][4])
{
    #pragma unroll
    for (int r = 0; r < 4; r++)
        *(float4*)(M + (i0 + r) * LDM + j0) = make_float4(v[r][0], v[r][1], v[r][2], v[r][3]);
    if (offdiag) {
        #pragma unroll
        for (int c = 0; c < 4; c++)
            *(float4*)(M + (j0 + c) * LDM + i0) = make_float4(v[0][c], v[1][c], v[2][c], v[3][c]);
    }
}

__global__ void __launch_bounds__(NTHREADS)
spd_log_cheb_ps_kernel(const float* __restrict__ xg, float* __restrict__ outg)
{
    extern __shared__ float sm[];
    float* Xs  = sm + 0 * MATN * LDM;   // X, then X~ (= T1)
    float* T2s = sm + 1 * MATN * LDM;
    float* T3s = sm + 2 * MATN * LDM;
    float* Ws  = sm + 3 * MATN * LDM;   // X*X, then W = T4
    float* B1  = sm + 4 * MATN * LDM;   // b3, then b1
    float* B2  = sm + 5 * MATN * LDM;   // b2
    float* rs  = sm + 6 * MATN * LDM;   // 64 X-rowsums, 64 X2-rowsums, 2 maxima

    const int t = threadIdx.x;
    const float* X = xg + (size_t)blockIdx.x * MATSZ;

    // ---- load X ----
    for (int e = t; e < MATSZ; e += NTHREADS)
        Xs[(e >> 6) * LDM + (e & 63)] = X[e];
    __syncthreads();

    // ---- tile assignment ----
    const bool active = (t < NTILES);
    int bi = 0, bj = 0;
    {
        int tt = active ? t : 0;
        while (tt >= 16 - bi) { tt -= 16 - bi; bi++; }
        bj = bi + tt;
    }
    const int i0 = bi * 4, j0 = bj * 4;
    const bool offdiag = (bi != bj);

    // ---- matmul 1: X2 = X * X ----
    if (active) {
        float s[4][4];
        mm_tile(Xs, Xs, i0, j0, s);
        store_tile_sym(Ws, i0, j0, offdiag, s);
    }
    __syncthreads();

    // ---- row abs-sums of X and X2 (Gershgorin bounds) ----
    if (t < MATN) {
        float sa = 0.f, sb = 0.f;
        #pragma unroll
        for (int j = 0; j < MATN; j++) {
            sa += fabsf(Xs[t * LDM + j]);
            sb += fabsf(Ws[t * LDM + j]);
        }
        rs[t] = sa;
        rs[64 + t] = sb;
    }
    __syncthreads();
    if (t < 32) {
        float ma = fmaxf(rs[t], rs[t + 32]);
        float mb = fmaxf(rs[64 + t], rs[96 + t]);
        #pragma unroll
        for (int o = 16; o > 0; o >>= 1) {
            ma = fmaxf(ma, __shfl_xor_sync(0xffffffffu, ma, o));
            mb = fmaxf(mb, __shfl_xor_sync(0xffffffffu, mb, o));
        }
        if (t == 0) { rs[128] = ma; rs[129] = mb; }
    }
    __syncthreads();

    // ---- interval, beta, Chebyshev coefficients, PS folding ----
    const float lo = 0.95f;
    const float gX = rs[128], g2 = rs[129];
    float bmax = fminf(gX * 1.0003f + 2e-3f, sqrtf(g2 * 1.001f) + 5e-3f);
    bmax = fmaxf(bmax, lo + 0.5f);
    const float cc     = 0.5f * (bmax + lo);
    const float dd     = 0.5f * (bmax - lo);
    const float inv_dd = 1.0f / dd;
    const float inv_d2 = inv_dd * inv_dd;
    const float ratio  = cc * inv_dd;
    const float beta   = ratio - sqrtf(ratio * ratio - 1.0f);

    float a[14];
    a[0] = logf(dd / (2.0f * beta));
    {
        float p = beta;                 // (-1)^{k+1} beta^k
        a[1] = 2.f * p;
        #pragma unroll
        for (int k = 2; k <= 13; k++) {
            p = -p * beta;
            a[k] = 2.f * p / (float)k;
        }
    }
    // fold a_k -> c[q][r] with T_q(W) T_r = (T_{4q+r} + T_{4q-r})/2
    float cf[4][4];
    #pragma unroll
    for (int q = 0; q < 4; q++)
        #pragma unroll
        for (int r = 0; r < 4; r++) cf[q][r] = 0.f;
    #pragma unroll
    for (int k = 13; k >= 4; k--) {
        const int q = k >> 2, r = k & 3;
        if (r > 0) { cf[q][r] = 2.f * a[k]; a[4 * q - r] -= a[k]; }
        else       { cf[q][0] = a[k]; }
    }
    #pragma unroll
    for (int r = 0; r < 4; r++) cf[0][r] = a[r];

    // ---- fused elementwise: T2 = (2X^2 - 4cX + 2c^2 I)/d^2 - I ; X~ = (X-c)/d ----
    const float t2diag = 2.f * cc * cc * inv_d2 - 1.f;
    for (int e = t; e < MATSZ; e += NTHREADS) {
        const int r = e >> 6, j = e & 63;
        const int idx = r * LDM + j;
        const float x  = Xs[idx];
        const float x2 = Ws[idx];
        const float dl = (r == j) ? 1.f : 0.f;
        T2s[idx] = (2.f * x2 - 4.f * cc * x) * inv_d2 + t2diag * dl;
        Xs[idx]  = (x - cc * dl) * inv_dd;
    }
    __syncthreads();

    // ---- matmul 2: T3 = 2 X~ T2 - X~ ----
    if (active) {
        float s[4][4], xt[4][4];
        mm_tile(Xs, T2s, i0, j0, s);
        load_tile(Xs, i0, j0, xt);
        float v[4][4];
        #pragma unroll
        for (int r = 0; r < 4; r++)
            #pragma unroll
            for (int c = 0; c < 4; c++) v[r][c] = 2.f * s[r][c] - xt[r][c];
        store_tile_sym(T3s, i0, j0, offdiag, v);
    }
    __syncthreads();

    // ---- matmul 3: W = T4 = 2 X~ T3 - T2 ; fused: B1 = b3 = P3 ----
    if (active) {
        float s[4][4], xt[4][4], t2[4][4], t3[4][4];
        mm_tile(Xs, T3s, i0, j0, s);
        load_tile(Xs, i0, j0, xt);
        load_tile(T2s, i0, j0, t2);
        load_tile(T3s, i0, j0, t3);
        float w[4][4], p3[4][4];
        #pragma unroll
        for (int r = 0; r < 4; r++)
            #pragma unroll
            for (int c = 0; c < 4; c++) {
                w[r][c] = 2.f * s[r][c] - t2[r][c];
                const float dl = ((i0 + r) == (j0 + c)) ? 1.f : 0.f;
                p3[r][c] = cf[3][0] * dl + cf[3][1] * xt[r][c]
                         + cf[3][2] * t2[r][c] + cf[3][3] * t3[r][c];
            }
        store_tile_sym(Ws, i0, j0, offdiag, w);
        store_tile_sym(B1, i0, j0, offdiag, p3);
    }
    __syncthreads();

    // ---- matmul 4: b2 = 2 W b3 + P2 -> B2 ----
    if (active) {
        float s[4][4], xt[4][4], t2[4][4], t3[4][4];
        mm_tile(Ws, B1, i0, j0, s);
        load_tile(Xs, i0, j0, xt);
        load_tile(T2s, i0, j0, t2);
        load_tile(T3s, i0, j0, t3);
        float v[4][4];
        #pragma unroll
        for (int r = 0; r < 4; r++)
            #pragma unroll
            for (int c = 0; c < 4; c++) {
                const float dl = ((i0 + r) == (j0 + c)) ? 1.f : 0.f;
                v[r][c] = 2.f * s[r][c] + cf[2][0] * dl + cf[2][1] * xt[r][c]
                        + cf[2][2] * t2[r][c] + cf[2][3] * t3[r][c];
            }
        store_tile_sym(B2, i0, j0, offdiag, v);
    }
    __syncthreads();

    // ---- matmul 5: b1 = 2 W b2 - b3 + P1 -> B1 (in-place per-tile) ----
    if (active) {
        float s[4][4], xt[4][4], t2[4][4], t3[4][4], b3[4][4];
        mm_tile(Ws, B2, i0, j0, s);
        load_tile(Xs, i0, j0, xt);
        load_tile(T2s, i0, j0, t2);
        load_tile(T3s, i0, j0, t3);
        load_tile(B1, i0, j0, b3);
        float v[4][4];
        #pragma unroll
        for (int r = 0; r < 4; r++)
            #pragma unroll
            for (int c = 0; c < 4; c++) {
                const float dl = ((i0 + r) == (j0 + c)) ? 1.f : 0.f;
                v[r][c] = 2.f * s[r][c] - b3[r][c] + cf[1][0] * dl + cf[1][1] * xt[r][c]
                        + cf[1][2] * t2[r][c] + cf[1][3] * t3[r][c];
            }
        store_tile_sym(B1, i0, j0, offdiag, v);
    }
    __syncthreads();

    // ---- matmul 6: S = W b1 + P0 - b2 -> output ----
    if (active) {
        float s[4][4], xt[4][4], t2[4][4], t3[4][4], b2[4][4];
        mm_tile(Ws, B1, i0, j0, s);
        load_tile(Xs, i0, j0, xt);
        load_tile(T2s, i0, j0, t2);
        load_tile(T3s, i0, j0, t3);
        load_tile(B2, i0, j0, b2);
        float* o = outg + (size_t)blockIdx.x * OUTSZ;
        #pragma unroll
        for (int r = 0; r < 4; r++)
            #pragma unroll
            for (int c = 0; c < 4; c++) {
                const int i = i0 + r, j = j0 + c;
                if (i <= j) {
                    const float dl = (i == j) ? 1.f : 0.f;
                    const float val = s[r][c] - b2[r][c] + cf[0][0] * dl
                                    + cf[0][1] * xt[r][c] + cf[0][2] * t2[r][c]
                                    + cf[0][3] * t3[r][c];
                    o[i * MATN - (i * (i - 1)) / 2 + (j - i)] = val;
                }
            }
    }
}

extern "C" void kernel_launch(void* const* d_in, const int* in_sizes, int n_in,
                              void* d_out, int out_size)
{
    const float* x = (const float*)d_in[0];
    float* out = (float*)d_out;
    const int B = in_sizes[0] / MATSZ;

    const int smem_bytes = (6 * MATN * LDM + 132) * (int)sizeof(float);
    cudaFuncSetAttribute(spd_log_cheb_ps_kernel,
                         cudaFuncAttributeMaxDynamicSharedMemorySize, smem_bytes);

    spd_log_cheb_ps_kernel<<<B, NTHREADS, smem_bytes>>>(x, out);
}